// round 9
// baseline (speedup 1.0000x reference)
#include <cuda_runtime.h>
#include <cuda_fp16.h>
#include <cstdint>

// Problem dims: B=4, S=4096, D=4096, E=64, K=2
#define NTOK 16384
#define DDIM 4096
#define NEXP 64
#define TPC  128                 // tokens per CTA
#define NCTA (NTOK / TPC)        // 128
#define THREADS 256
#define KC   64                  // K per chunk
#define NCHUNK (DDIM / KC)       // 64

// Output layout (flattened f32): idx[2N], scores[2N], probs[64N], zloss[1], imp[64], load[64]
#define OFF_IDX     0
#define OFF_SCORES  (NTOK * 2)
#define OFF_PROBS   (NTOK * 4)
#define OFF_ZLOSS   (NTOK * 4 + NTOK * NEXP)
#define OFF_IMP     (OFF_ZLOSS + 1)
#define OFF_LOAD    (OFF_IMP + NEXP)

// B staging: fp16, 2 levels, pitch 144B (conflict-free ldmatrix), 4-stage ring
#define BPITCH 144
#define LEVSZ  (NEXP * BPITCH)       // 9216
#define BSTAGE (2 * LEVSZ)           // 18432
#define NBSTG  4
// A16: converted A, fp16, 2 levels, 128 rows x 64 cols, pitch 144, double buffer
#define ALEVSZ (TPC * BPITCH)        // 18432
#define A16SZ  (2 * ALEVSZ)          // 36864
#define A16OFF (NBSTG * BSTAGE)      // 73728
#define SMEM_TOTAL (A16OFF + 2 * A16SZ)   // 147456

#define SCALE   4096.0f              // 2^12 residual scaling
#define INVSCALE (1.0f / 4096.0f)

// Scratch globals
__device__ unsigned short g_Wh[NEXP * DDIM];
__device__ unsigned short g_Wl[NEXP * DDIM];   // fp16(2^12 * residual)
__device__ float g_acc[2 * NEXP + 1];
__device__ unsigned int g_done;

// ---------------------------------------------------------------------------
__device__ __forceinline__ uint32_t smem_u32(const void* p) {
    uint32_t a;
    asm("{ .reg .u64 t; cvta.to.shared.u64 t, %1; cvt.u32.u64 %0, t; }" : "=r"(a) : "l"(p));
    return a;
}

#define CPA16(sm, gp) \
    asm volatile("cp.async.cg.shared.global [%0], [%1], 16;" :: "r"(sm), "l"(gp))
#define CPC()  asm volatile("cp.async.commit_group;" ::: "memory")
#define CPW2() asm volatile("cp.async.wait_group 2;" ::: "memory")
#define CPW1() asm volatile("cp.async.wait_group 1;" ::: "memory")
#define CPW0() asm volatile("cp.async.wait_group 0;" ::: "memory")

#define LDSM4(R, a) \
    asm volatile("ldmatrix.sync.aligned.m8n8.x4.shared.b16 {%0,%1,%2,%3}, [%4];" \
        : "=r"((R)[0]), "=r"((R)[1]), "=r"((R)[2]), "=r"((R)[3]) : "r"(a))

#define MMA(C, A, B0, B1) \
    asm volatile("mma.sync.aligned.m16n8k16.row.col.f32.f16.f16.f32 " \
        "{%0,%1,%2,%3}, {%4,%5,%6,%7}, {%8,%9}, {%0,%1,%2,%3};" \
        : "+f"((C)[0]), "+f"((C)[1]), "+f"((C)[2]), "+f"((C)[3]) \
        : "r"((A)[0]), "r"((A)[1]), "r"((A)[2]), "r"((A)[3]), "r"(B0), "r"(B1))

__device__ __forceinline__ void splitAx(float2 v, unsigned& h, unsigned& l) {
    __half2 hh = __float22half2_rn(v);
    float2 back = __half22float2(hh);
    float2 r = make_float2((v.x - back.x) * SCALE, (v.y - back.y) * SCALE);
    __half2 ll = __float22half2_rn(r);
    h = *reinterpret_cast<unsigned*>(&hh);
    l = *reinterpret_cast<unsigned*>(&ll);
}

__device__ __forceinline__ bool better(float v1, int i1, float v2, int i2) {
    return (v1 > v2) || (v1 == v2 && i1 < i2);
}

// ---------------------------------------------------------------------------
// Kernel 1: split W into fp16 high + scaled-residual levels; zero accumulators
// ---------------------------------------------------------------------------
__global__ void prep_kernel(const float* __restrict__ W) {
    int i = blockIdx.x * 256 + threadIdx.x;
    if (i < NEXP * DDIM) {
        float w = W[i];
        __half h = __float2half_rn(w);
        float r = (w - __half2float(h)) * SCALE;
        __half l = __float2half_rn(r);
        g_Wh[i] = *reinterpret_cast<unsigned short*>(&h);
        g_Wl[i] = *reinterpret_cast<unsigned short*>(&l);
    }
    if (i < 2 * NEXP + 1) g_acc[i] = 0.0f;
    if (i == 0) g_done = 0u;
}

// ---------------------------------------------------------------------------
// per-token-row routing epilogue (quad of 4 lanes owns one row of 64 logits)
// ---------------------------------------------------------------------------
__device__ __forceinline__ void row_epilogue(const float v[16], float p[16],
                                             int token, int qc, int lane,
                                             float* __restrict__ out,
                                             float* s_cnt, float& zz) {
    float mx = v[0];
#pragma unroll
    for (int i = 1; i < 16; ++i) mx = fmaxf(mx, v[i]);
    mx = fmaxf(mx, __shfl_xor_sync(0xffffffffu, mx, 1));
    mx = fmaxf(mx, __shfl_xor_sync(0xffffffffu, mx, 2));
    float s = 0.0f;
#pragma unroll
    for (int i = 0; i < 16; ++i) { p[i] = __expf(v[i] - mx); s += p[i]; }
    s += __shfl_xor_sync(0xffffffffu, s, 1);
    s += __shfl_xor_sync(0xffffffffu, s, 2);
    const float inv = 1.0f / s;
#pragma unroll
    for (int i = 0; i < 16; ++i) p[i] *= inv;
    float* po = out + OFF_PROBS + (size_t)token * NEXP;
#pragma unroll
    for (int j = 0; j < 8; ++j)
        *reinterpret_cast<float2*>(po + j * 8 + qc) = make_float2(p[2 * j], p[2 * j + 1]);
    // local top-2 (ascending col order; strict > keeps lowest index on ties)
    float av = -3.4e38f, bv = -3.4e38f; int ai = 0, bi = 0;
#pragma unroll
    for (int j = 0; j < 8; ++j)
#pragma unroll
        for (int i = 0; i < 2; ++i) {
            float val = v[j * 2 + i];
            int col = j * 8 + qc + i;
            if (val > av)      { bv = av; bi = ai; av = val; ai = col; }
            else if (val > bv) { bv = val; bi = col; }
        }
#pragma unroll
    for (int o = 1; o <= 2; o <<= 1) {
        float av2 = __shfl_xor_sync(0xffffffffu, av, o);
        int   ai2 = __shfl_xor_sync(0xffffffffu, ai, o);
        float bv2 = __shfl_xor_sync(0xffffffffu, bv, o);
        int   bi2 = __shfl_xor_sync(0xffffffffu, bi, o);
        if (better(av2, ai2, av, ai)) {
            bool s2 = better(bv2, bi2, av, ai);
            float nbv = s2 ? bv2 : av; int nbi = s2 ? bi2 : ai;
            av = av2; ai = ai2; bv = nbv; bi = nbi;
        } else if (better(av2, ai2, bv, bi)) { bv = av2; bi = ai2; }
    }
    if ((lane & 3) == 0) {
        float ex  = __expf(bv - av);
        float sc0 = 1.0f / (1.0f + ex);
        out[OFF_IDX + token * 2]        = (float)ai;
        out[OFF_IDX + token * 2 + 1]    = (float)bi;
        out[OFF_SCORES + token * 2]     = sc0;
        out[OFF_SCORES + token * 2 + 1] = ex * sc0;
        atomicAdd(&s_cnt[ai], 1.0f);
        atomicAdd(&s_cnt[bi], 1.0f);
    }
    float z = mx + __logf(s);
    zz += z * z;
}

// ---------------------------------------------------------------------------
// Kernel 2: fused fp16-split GEMM + routing. Hot loop = pure LDSM + MMA.
// A converted fp32->fp16(hi/lo) in registers (overlapping MMA), staged through
// a double-buffered A16 smem tile; B via 4-stage cp.async ring.
// ---------------------------------------------------------------------------
__global__ void __launch_bounds__(THREADS, 1)
router_kernel(const float* __restrict__ x, float* __restrict__ out) {
    extern __shared__ __align__(16) char smem[];
    const uint32_t sb = smem_u32(smem);
    const int tid = threadIdx.x, w = tid >> 5, lane = tid & 31;
    const int g = lane >> 2, qc = (lane & 3) * 2;
    const int token0 = blockIdx.x * TPC;

    const char* whb = reinterpret_cast<const char*>(g_Wh);
    const char* wlb = reinterpret_cast<const char*>(g_Wl);

    // B ldmatrix lane address (proven rounds 3/5/8)
    const int n_in = (lane & 7) | ((lane & 16) >> 1);
    const int lmoff = n_in * BPITCH + ((lane & 8) << 1);
    // A ldmatrix lane address (canonical m16k16: rows lane&15, k-half lane&16)
    const uint32_t aln = sb + A16OFF + (uint32_t)((w * 16 + (lane & 15)) * BPITCH + (lane & 16));

    // A convert/store mapping: thread handles 8 float4 (rows tid>>4 + 16*ps)
    const int arow = tid >> 4, aseg = tid & 15;
    const float* xsrc = x + (size_t)(token0 + arow) * DDIM + aseg * 4;
    const uint32_t asts = sb + A16OFF + (uint32_t)(arow * BPITCH + aseg * 8);

    float C[8][4], Clo[8][4];
#pragma unroll
    for (int j = 0; j < 8; ++j)
#pragma unroll
        for (int i = 0; i < 4; ++i) { C[j][i] = 0.0f; Clo[j][i] = 0.0f; }

    unsigned aqh[16], aql[16];   // pending converted A chunk (8 float4 worth)

#define LDGA_CONVERT(k0)                                                          \
    do {                                                                          \
        _Pragma("unroll")                                                         \
        for (int ps = 0; ps < 8; ++ps) {                                          \
            const float4 vv = __ldcs(reinterpret_cast<const float4*>(             \
                xsrc + (size_t)(ps * 16) * DDIM + (k0)));                         \
            splitAx(make_float2(vv.x, vv.y), aqh[2 * ps], aql[2 * ps]);           \
            splitAx(make_float2(vv.z, vv.w), aqh[2 * ps + 1], aql[2 * ps + 1]);   \
        }                                                                         \
    } while (0)

#define STS_A16(bufp)                                                             \
    do {                                                                          \
        const uint32_t _ab = asts + (uint32_t)(bufp) * A16SZ;                     \
        _Pragma("unroll")                                                         \
        for (int ps = 0; ps < 8; ++ps) {                                          \
            asm volatile("st.shared.v2.b32 [%0], {%1, %2};"                       \
                :: "r"(_ab + ps * (16 * BPITCH)),                                 \
                   "r"(aqh[2 * ps]), "r"(aqh[2 * ps + 1]));                       \
            asm volatile("st.shared.v2.b32 [%0], {%1, %2};"                       \
                :: "r"(_ab + ps * (16 * BPITCH) + ALEVSZ),                        \
                   "r"(aql[2 * ps]), "r"(aql[2 * ps + 1]));                       \
        }                                                                         \
    } while (0)

    // B: 1024 16B segs/stage, 4 per thread
#define ISSUE_B(sidx, k0)                                                         \
    do {                                                                          \
        const uint32_t _bs = sb + (uint32_t)(sidx) * BSTAGE;                      \
        _Pragma("unroll")                                                         \
        for (int ps = 0; ps < 4; ++ps) {                                          \
            int idx = tid + ps * 256;                                             \
            int lev = idx >> 9, rem = idx & 511, row = rem >> 3, seg = rem & 7;   \
            const char* src = (lev == 0 ? whb : wlb)                              \
                              + ((size_t)row * DDIM + (k0) + seg * 8) * 2;        \
            CPA16(_bs + lev * LEVSZ + row * BPITCH + seg * 16, src);              \
        }                                                                         \
        CPC();                                                                    \
    } while (0)

    // ---- prologue ----
    LDGA_CONVERT(0);
    STS_A16(0);                  // chunk 0 -> A16 buffer 0 (pre-barrier; iter-0 sync publishes)
    LDGA_CONVERT(KC);            // chunk 1 pending in regs
    ISSUE_B(0, 0);
    ISSUE_B(1, KC);

#pragma unroll 1
    for (int c = 0; c < NCHUNK; ++c) {
        if (c + 2 < NCHUNK) {
            ISSUE_B((c + 2) & 3, (c + 2) * KC);
            CPW2();
        } else if (c + 1 < NCHUNK) {
            CPW1();
        } else {
            CPW0();
        }
        __syncthreads();
        // publish pending A chunk c+1 into buffer (c+1)&1 (readers of that
        // parity, MMA(c-1), all finished before this barrier)
        if (c + 1 < NCHUNK) STS_A16((c + 1) & 1);

        const uint32_t bB = sb + (uint32_t)(c & 3) * BSTAGE + lmoff;
        const uint32_t aB = aln + (uint32_t)(c & 1) * A16SZ;

#pragma unroll
        for (int ks = 0; ks < 4; ++ks) {
            unsigned ah[4], al[4];
            LDSM4(ah, aB + ks * 32);
            LDSM4(al, aB + ks * 32 + ALEVSZ);
            unsigned bh[16], bl[16];
#pragma unroll
            for (int p = 0; p < 4; ++p) {
                const uint32_t ba = bB + p * (16 * BPITCH) + ks * 32;
                LDSM4(bh + 4 * p, ba);
                LDSM4(bl + 4 * p, ba + LEVSZ);
            }
#pragma unroll
            for (int j = 0; j < 8; ++j) MMA(C[j],   ah, bh[2 * j], bh[2 * j + 1]);
#pragma unroll
            for (int j = 0; j < 8; ++j) MMA(Clo[j], ah, bl[2 * j], bl[2 * j + 1]);
#pragma unroll
            for (int j = 0; j < 8; ++j) MMA(Clo[j], al, bh[2 * j], bh[2 * j + 1]);
        }
        // fetch + convert chunk c+2 (ALU overlaps the MMA stream above)
        if (c + 2 < NCHUNK) LDGA_CONVERT((c + 2) * KC);
    }
    __syncthreads();   // GEMM done; smem becomes reduction scratch

    // ---------------- epilogue (round-5/8 proven) ----------------
    float* s_imp = reinterpret_cast<float*>(smem);
    float* s_cnt = s_imp + NEXP;
    float* s_z   = s_cnt + NEXP;
    if (tid < NEXP) { s_imp[tid] = 0.0f; s_cnt[tid] = 0.0f; }
    if (tid == NEXP * 2) *s_z = 0.0f;
    __syncthreads();

    const int token_r0 = token0 + w * 16 + g;
    float v[16], p[16], imp[16];
    float zz = 0.0f;
#pragma unroll
    for (int i = 0; i < 16; ++i) imp[i] = 0.0f;

    // row g (C lanes 0,1)
#pragma unroll
    for (int j = 0; j < 8; ++j) {
        v[2 * j]     = fmaf(Clo[j][0], INVSCALE, C[j][0]);
        v[2 * j + 1] = fmaf(Clo[j][1], INVSCALE, C[j][1]);
    }
    row_epilogue(v, p, token_r0, qc, lane, out, s_cnt, zz);
#pragma unroll
    for (int i = 0; i < 16; ++i) imp[i] += p[i];

    // row g+8 (C lanes 2,3)
#pragma unroll
    for (int j = 0; j < 8; ++j) {
        v[2 * j]     = fmaf(Clo[j][2], INVSCALE, C[j][2]);
        v[2 * j + 1] = fmaf(Clo[j][3], INVSCALE, C[j][3]);
    }
    row_epilogue(v, p, token_r0 + 8, qc, lane, out, s_cnt, zz);
#pragma unroll
    for (int i = 0; i < 16; ++i) imp[i] += p[i];

    // importance across the 8 row-groups (same lane&3)
#pragma unroll
    for (int o = 4; o <= 16; o <<= 1)
#pragma unroll
        for (int i = 0; i < 16; ++i)
            imp[i] += __shfl_xor_sync(0xffffffffu, imp[i], o);
    if (lane < 4) {
#pragma unroll
        for (int j = 0; j < 8; ++j) {
            atomicAdd(&s_imp[j * 8 + qc],     imp[2 * j]);
            atomicAdd(&s_imp[j * 8 + qc + 1], imp[2 * j + 1]);
        }
    }
#pragma unroll
    for (int o = 4; o <= 16; o <<= 1) zz += __shfl_xor_sync(0xffffffffu, zz, o);
    if (lane == 0) atomicAdd(s_z, zz);
    __syncthreads();

    if (tid < NEXP) {
        atomicAdd(&g_acc[tid], s_imp[tid]);
        atomicAdd(&g_acc[NEXP + tid], s_cnt[tid]);
    }
    if (tid == NEXP * 2) atomicAdd(&g_acc[2 * NEXP], *s_z);

    __syncthreads();
    if (tid == 0) {
        __threadfence();
        unsigned prev = atomicAdd(&g_done, 1u);
        if (prev == NCTA - 1) {
#pragma unroll
            for (int i = 0; i < NEXP; ++i) {
                out[OFF_IMP + i]  = __ldcg(&g_acc[i]) * (1.0f / (float)NTOK);
                out[OFF_LOAD + i] = __ldcg(&g_acc[NEXP + i]) * (1.0f / (float)(2 * NTOK));
            }
            out[OFF_ZLOSS] = __ldcg(&g_acc[2 * NEXP]) * (1.0f / (float)NTOK);
        }
    }
}

// ---------------------------------------------------------------------------
extern "C" void kernel_launch(void* const* d_in, const int* in_sizes, int n_in,
                              void* d_out, int out_size) {
    const float* x = (const float*)d_in[0];   // [4,4096,4096] f32
    const float* W = (const float*)d_in[1];   // [64,4096] f32
    float* out = (float*)d_out;

    cudaFuncSetAttribute(router_kernel, cudaFuncAttributeMaxDynamicSharedMemorySize,
                         SMEM_TOTAL);

    prep_kernel<<<(NEXP * DDIM + 255) / 256, 256>>>(W);
    router_kernel<<<NCTA, THREADS, SMEM_TOTAL>>>(x, out);
}

// round 10
// speedup vs baseline: 1.4781x; 1.4781x over previous
#include <cuda_runtime.h>
#include <cuda_fp16.h>
#include <cstdint>

// Problem dims: B=4, S=4096, D=4096, E=64, K=2
#define NTOK 16384
#define DDIM 4096
#define NEXP 64
#define TPC  128                 // tokens per CTA
#define NCTA (NTOK / TPC)        // 128
#define THREADS 256
#define KC   64                  // K per chunk
#define NCHUNK (DDIM / KC)       // 64
#define NSTAGE 4

// Output layout (flattened f32): idx[2N], scores[2N], probs[64N], zloss[1], imp[64], load[64]
#define OFF_IDX     0
#define OFF_SCORES  (NTOK * 2)
#define OFF_PROBS   (NTOK * 4)
#define OFF_ZLOSS   (NTOK * 4 + NTOK * NEXP)
#define OFF_IMP     (OFF_ZLOSS + 1)
#define OFF_LOAD    (OFF_IMP + NEXP)

// smem staging per stage: A fp32 (pitch 288B) + B fp16 2 levels (pitch 144B)
#define APITCH 288
#define ASTAGE (TPC * APITCH)        // 36864
#define BPITCH 144
#define LEVSZ  (NEXP * BPITCH)       // 9216
#define BSTAGE (2 * LEVSZ)           // 18432
#define STAGE  (ASTAGE + BSTAGE)     // 55296
#define SMEM_TOTAL (NSTAGE * STAGE)  // 221184

#define SCALE   4096.0f              // 2^12 residual scaling
#define INVSCALE (1.0f / 4096.0f)

// Scratch globals
__device__ unsigned short g_Wh[NEXP * DDIM];
__device__ unsigned short g_Wl[NEXP * DDIM];   // fp16(2^12 * residual)
__device__ float g_acc[2 * NEXP + 1];
__device__ unsigned int g_done;

// ---------------------------------------------------------------------------
__device__ __forceinline__ uint32_t smem_u32(const void* p) {
    uint32_t a;
    asm("{ .reg .u64 t; cvta.to.shared.u64 t, %1; cvt.u32.u64 %0, t; }" : "=r"(a) : "l"(p));
    return a;
}

#define CPA16(sm, gp) \
    asm volatile("cp.async.cg.shared.global [%0], [%1], 16;" :: "r"(sm), "l"(gp))
#define CPC()  asm volatile("cp.async.commit_group;" ::: "memory")
#define CPW2() asm volatile("cp.async.wait_group 2;" ::: "memory")
#define CPW1() asm volatile("cp.async.wait_group 1;" ::: "memory")
#define CPW0() asm volatile("cp.async.wait_group 0;" ::: "memory")

#define LDSM4(R, a) \
    asm volatile("ldmatrix.sync.aligned.m8n8.x4.shared.b16 {%0,%1,%2,%3}, [%4];" \
        : "=r"((R)[0]), "=r"((R)[1]), "=r"((R)[2]), "=r"((R)[3]) : "r"(a))

#define MMA(C, A, B0, B1) \
    asm volatile("mma.sync.aligned.m16n8k16.row.col.f32.f16.f16.f32 " \
        "{%0,%1,%2,%3}, {%4,%5,%6,%7}, {%8,%9}, {%0,%1,%2,%3};" \
        : "+f"((C)[0]), "+f"((C)[1]), "+f"((C)[2]), "+f"((C)[3]) \
        : "r"((A)[0]), "r"((A)[1]), "r"((A)[2]), "r"((A)[3]), "r"(B0), "r"(B1))

__device__ __forceinline__ void splitAx(float2 v, unsigned& h, unsigned& l) {
    __half2 hh = __float22half2_rn(v);
    float2 back = __half22float2(hh);
    float2 r = make_float2((v.x - back.x) * SCALE, (v.y - back.y) * SCALE);
    __half2 ll = __float22half2_rn(r);
    h = *reinterpret_cast<unsigned*>(&hh);
    l = *reinterpret_cast<unsigned*>(&ll);
}

__device__ __forceinline__ bool better(float v1, int i1, float v2, int i2) {
    return (v1 > v2) || (v1 == v2 && i1 < i2);
}

// ---------------------------------------------------------------------------
// Kernel 1: split W into fp16 high + scaled-residual levels; zero accumulators
// ---------------------------------------------------------------------------
__global__ void prep_kernel(const float* __restrict__ W) {
    int i = blockIdx.x * 256 + threadIdx.x;
    if (i < NEXP * DDIM) {
        float w = W[i];
        __half h = __float2half_rn(w);
        float r = (w - __half2float(h)) * SCALE;
        __half l = __float2half_rn(r);
        g_Wh[i] = *reinterpret_cast<unsigned short*>(&h);
        g_Wl[i] = *reinterpret_cast<unsigned short*>(&l);
    }
    if (i < 2 * NEXP + 1) g_acc[i] = 0.0f;
    if (i == 0) g_done = 0u;
}

// ---------------------------------------------------------------------------
// per-token-row routing epilogue (quad of 4 lanes owns one row of 64 logits)
// ---------------------------------------------------------------------------
__device__ __forceinline__ void row_epilogue(const float v[16], float p[16],
                                             int token, int qc, int lane,
                                             float* __restrict__ out,
                                             float* s_cnt, float& zz) {
    float mx = v[0];
#pragma unroll
    for (int i = 1; i < 16; ++i) mx = fmaxf(mx, v[i]);
    mx = fmaxf(mx, __shfl_xor_sync(0xffffffffu, mx, 1));
    mx = fmaxf(mx, __shfl_xor_sync(0xffffffffu, mx, 2));
    float s = 0.0f;
#pragma unroll
    for (int i = 0; i < 16; ++i) { p[i] = __expf(v[i] - mx); s += p[i]; }
    s += __shfl_xor_sync(0xffffffffu, s, 1);
    s += __shfl_xor_sync(0xffffffffu, s, 2);
    const float inv = 1.0f / s;
#pragma unroll
    for (int i = 0; i < 16; ++i) p[i] *= inv;
    float* po = out + OFF_PROBS + (size_t)token * NEXP;
#pragma unroll
    for (int j = 0; j < 8; ++j)
        *reinterpret_cast<float2*>(po + j * 8 + qc) = make_float2(p[2 * j], p[2 * j + 1]);
    // local top-2 (ascending col order; strict > keeps lowest index on ties)
    float av = -3.4e38f, bv = -3.4e38f; int ai = 0, bi = 0;
#pragma unroll
    for (int j = 0; j < 8; ++j)
#pragma unroll
        for (int i = 0; i < 2; ++i) {
            float val = v[j * 2 + i];
            int col = j * 8 + qc + i;
            if (val > av)      { bv = av; bi = ai; av = val; ai = col; }
            else if (val > bv) { bv = val; bi = col; }
        }
#pragma unroll
    for (int o = 1; o <= 2; o <<= 1) {
        float av2 = __shfl_xor_sync(0xffffffffu, av, o);
        int   ai2 = __shfl_xor_sync(0xffffffffu, ai, o);
        float bv2 = __shfl_xor_sync(0xffffffffu, bv, o);
        int   bi2 = __shfl_xor_sync(0xffffffffu, bi, o);
        if (better(av2, ai2, av, ai)) {
            bool s2 = better(bv2, bi2, av, ai);
            float nbv = s2 ? bv2 : av; int nbi = s2 ? bi2 : ai;
            av = av2; ai = ai2; bv = nbv; bi = nbi;
        } else if (better(av2, ai2, bv, bi)) { bv = av2; bi = ai2; }
    }
    if ((lane & 3) == 0) {
        float ex  = __expf(bv - av);
        float sc0 = 1.0f / (1.0f + ex);
        out[OFF_IDX + token * 2]        = (float)ai;
        out[OFF_IDX + token * 2 + 1]    = (float)bi;
        out[OFF_SCORES + token * 2]     = sc0;
        out[OFF_SCORES + token * 2 + 1] = ex * sc0;
        atomicAdd(&s_cnt[ai], 1.0f);
        atomicAdd(&s_cnt[bi], 1.0f);
    }
    float z = mx + __logf(s);
    zz += z * z;
}

// ---------------------------------------------------------------------------
// Kernel 2: fused 3-way fp16-split GEMM (mma.sync) + routing epilogue.
// 256 threads, 8 warps, warp = 16 tokens x 64 experts.
// 4-stage cp.async ring, single __syncthreads per chunk.
// A fragments for the whole chunk prepared up-front (batched LDS + split);
// B LDSM staggered across the three MMA sweeps.
// ---------------------------------------------------------------------------
__global__ void __launch_bounds__(THREADS, 1)
router_kernel(const float* __restrict__ x, float* __restrict__ out) {
    extern __shared__ __align__(16) char smem[];
    const uint32_t sb = smem_u32(smem);
    const int tid = threadIdx.x, w = tid >> 5, lane = tid & 31;
    const int g = lane >> 2, qc = (lane & 3) * 2;
    const int token0 = blockIdx.x * TPC;

    const char* xbytes = reinterpret_cast<const char*>(x);
    const char* whb = reinterpret_cast<const char*>(g_Wh);
    const char* wlb = reinterpret_cast<const char*>(g_Wl);

    // ldmatrix per-lane address component (layout proven rounds 3/5/8)
    const int n_in = (lane & 7) | ((lane & 16) >> 1);
    const int lmoff = n_in * BPITCH + ((lane & 8) << 1);

    // A fragment smem addresses (rows w*16+g and +8)
    const uint32_t arow0 = sb + (uint32_t)(w * 16 + g) * APITCH + (uint32_t)qc * 4;
    const uint32_t arow1 = arow0 + 8u * APITCH;

    float C[8][4], Clo[8][4];
#pragma unroll
    for (int j = 0; j < 8; ++j)
#pragma unroll
        for (int i = 0; i < 4; ++i) { C[j][i] = 0.0f; Clo[j][i] = 0.0f; }

    // A: 2048 16B segs/stage, 8/thread. B: 1024 segs (2 levels), 4/thread.
#define ISSUE_STAGE(sidx, k0)                                                        \
    do {                                                                             \
        const uint32_t _stg = sb + (uint32_t)(sidx) * STAGE;                         \
        const uint32_t _sbB = _stg + ASTAGE;                                         \
        _Pragma("unroll")                                                            \
        for (int ps = 0; ps < 8; ++ps) {                                             \
            int idx = tid + ps * 256;                                                \
            int row = idx >> 4, seg = idx & 15;                                      \
            CPA16(_stg + row * APITCH + seg * 16,                                    \
                  xbytes + ((size_t)(token0 + row) * DDIM + (k0) + seg * 4) * 4);    \
        }                                                                            \
        _Pragma("unroll")                                                            \
        for (int ps = 0; ps < 4; ++ps) {                                             \
            int idx = tid + ps * 256;                                                \
            int lev = idx >> 9, rem = idx & 511, row = rem >> 3, seg = rem & 7;      \
            const char* src = (lev == 0 ? whb : wlb)                                 \
                              + ((size_t)row * DDIM + (k0) + seg * 8) * 2;           \
            CPA16(_sbB + lev * LEVSZ + row * BPITCH + seg * 16, src);                \
        }                                                                            \
        CPC();                                                                       \
    } while (0)

    // prologue: stages 0, 1
    ISSUE_STAGE(0, 0);
    ISSUE_STAGE(1, KC);

#pragma unroll 1
    for (int c = 0; c < NCHUNK; ++c) {
        const int bufc = c & 3;
        // fill buffer (c+2)%4: held stage c-2, fully consumed before iter c-1's
        // barrier -> safe with the single sync below.
        if (c + 2 < NCHUNK) {
            ISSUE_STAGE((c + 2) & 3, (c + 2) * KC);
            CPW2();
        } else if (c + 1 < NCHUNK) {
            CPW1();
        } else {
            CPW0();
        }
        __syncthreads();

        const uint32_t stg = sb + (uint32_t)bufc * STAGE;
        const uint32_t a0 = arow0 + (uint32_t)bufc * STAGE;
        const uint32_t a1 = arow1 + (uint32_t)bufc * STAGE;
        const uint32_t bbase = stg + ASTAGE + lmoff;

        // ---- prepare ALL A fragments for this chunk (batched; one-time cost) ----
        unsigned ah[4][4], al[4][4];
#pragma unroll
        for (int ks = 0; ks < 4; ++ks) {
            float2 f0, f1, f2, f3;
            const uint32_t ka = (uint32_t)(ks * 64);
            asm volatile("ld.shared.v2.f32 {%0,%1}, [%2];" : "=f"(f0.x), "=f"(f0.y) : "r"(a0 + ka));
            asm volatile("ld.shared.v2.f32 {%0,%1}, [%2];" : "=f"(f1.x), "=f"(f1.y) : "r"(a1 + ka));
            asm volatile("ld.shared.v2.f32 {%0,%1}, [%2];" : "=f"(f2.x), "=f"(f2.y) : "r"(a0 + ka + 32));
            asm volatile("ld.shared.v2.f32 {%0,%1}, [%2];" : "=f"(f3.x), "=f"(f3.y) : "r"(a1 + ka + 32));
            splitAx(f0, ah[ks][0], al[ks][0]);
            splitAx(f1, ah[ks][1], al[ks][1]);
            splitAx(f2, ah[ks][2], al[ks][2]);
            splitAx(f3, ah[ks][3], al[ks][3]);
        }

        // ---- MMA stream: LDSM staggered across the three sweeps ----
#pragma unroll
        for (int ks = 0; ks < 4; ++ks) {
            const uint32_t ba = bbase + ks * 32;
            unsigned bh[16];
#pragma unroll
            for (int p = 0; p < 4; ++p) LDSM4(bh + 4 * p, ba + p * (16 * BPITCH));
#pragma unroll
            for (int j = 0; j < 8; ++j) MMA(C[j], ah[ks], bh[2 * j], bh[2 * j + 1]);
            unsigned bl[16];
#pragma unroll
            for (int p = 0; p < 4; ++p) LDSM4(bl + 4 * p, ba + p * (16 * BPITCH) + LEVSZ);
#pragma unroll
            for (int j = 0; j < 8; ++j) MMA(Clo[j], al[ks], bh[2 * j], bh[2 * j + 1]);
#pragma unroll
            for (int j = 0; j < 8; ++j) MMA(Clo[j], ah[ks], bl[2 * j], bl[2 * j + 1]);
        }
    }
    __syncthreads();   // GEMM done; smem becomes reduction scratch

    // ---------------- epilogue (round-5/8 proven) ----------------
    float* s_imp = reinterpret_cast<float*>(smem);
    float* s_cnt = s_imp + NEXP;
    float* s_z   = s_cnt + NEXP;
    if (tid < NEXP) { s_imp[tid] = 0.0f; s_cnt[tid] = 0.0f; }
    if (tid == NEXP * 2) *s_z = 0.0f;
    __syncthreads();

    const int token_r0 = token0 + w * 16 + g;
    float v[16], p[16], imp[16];
    float zz = 0.0f;
#pragma unroll
    for (int i = 0; i < 16; ++i) imp[i] = 0.0f;

    // row g (C lanes 0,1)
#pragma unroll
    for (int j = 0; j < 8; ++j) {
        v[2 * j]     = fmaf(Clo[j][0], INVSCALE, C[j][0]);
        v[2 * j + 1] = fmaf(Clo[j][1], INVSCALE, C[j][1]);
    }
    row_epilogue(v, p, token_r0, qc, lane, out, s_cnt, zz);
#pragma unroll
    for (int i = 0; i < 16; ++i) imp[i] += p[i];

    // row g+8 (C lanes 2,3)
#pragma unroll
    for (int j = 0; j < 8; ++j) {
        v[2 * j]     = fmaf(Clo[j][2], INVSCALE, C[j][2]);
        v[2 * j + 1] = fmaf(Clo[j][3], INVSCALE, C[j][3]);
    }
    row_epilogue(v, p, token_r0 + 8, qc, lane, out, s_cnt, zz);
#pragma unroll
    for (int i = 0; i < 16; ++i) imp[i] += p[i];

    // importance across the 8 row-groups (same lane&3)
#pragma unroll
    for (int o = 4; o <= 16; o <<= 1)
#pragma unroll
        for (int i = 0; i < 16; ++i)
            imp[i] += __shfl_xor_sync(0xffffffffu, imp[i], o);
    if (lane < 4) {
#pragma unroll
        for (int j = 0; j < 8; ++j) {
            atomicAdd(&s_imp[j * 8 + qc],     imp[2 * j]);
            atomicAdd(&s_imp[j * 8 + qc + 1], imp[2 * j + 1]);
        }
    }
#pragma unroll
    for (int o = 4; o <= 16; o <<= 1) zz += __shfl_xor_sync(0xffffffffu, zz, o);
    if (lane == 0) atomicAdd(s_z, zz);
    __syncthreads();

    if (tid < NEXP) {
        atomicAdd(&g_acc[tid], s_imp[tid]);
        atomicAdd(&g_acc[NEXP + tid], s_cnt[tid]);
    }
    if (tid == NEXP * 2) atomicAdd(&g_acc[2 * NEXP], *s_z);

    __syncthreads();
    if (tid == 0) {
        __threadfence();
        unsigned prev = atomicAdd(&g_done, 1u);
        if (prev == NCTA - 1) {
#pragma unroll
            for (int i = 0; i < NEXP; ++i) {
                out[OFF_IMP + i]  = __ldcg(&g_acc[i]) * (1.0f / (float)NTOK);
                out[OFF_LOAD + i] = __ldcg(&g_acc[NEXP + i]) * (1.0f / (float)(2 * NTOK));
            }
            out[OFF_ZLOSS] = __ldcg(&g_acc[2 * NEXP]) * (1.0f / (float)NTOK);
        }
    }
}

// ---------------------------------------------------------------------------
extern "C" void kernel_launch(void* const* d_in, const int* in_sizes, int n_in,
                              void* d_out, int out_size) {
    const float* x = (const float*)d_in[0];   // [4,4096,4096] f32
    const float* W = (const float*)d_in[1];   // [64,4096] f32
    float* out = (float*)d_out;

    cudaFuncSetAttribute(router_kernel, cudaFuncAttributeMaxDynamicSharedMemorySize,
                         SMEM_TOTAL);

    prep_kernel<<<(NEXP * DDIM + 255) / 256, 256>>>(W);
    router_kernel<<<NCTA, THREADS, SMEM_TOTAL>>>(x, out);
}